// round 15
// baseline (speedup 1.0000x reference)
#include <cuda_runtime.h>
#include <cuda_fp16.h>
#include <cuda_bf16.h>

#define RES   256
#define RANK  12
#define OUTC  8

#define HU(h)  (*(unsigned int*)&(h))
#define U2H(u) (*(__half2*)&(u))

// Corner-quad records: per (plane,y,x) a 64B record {v00,v01,v10,v11} of
// fp16x8 projected features (+ bias/3 folded in), border clamp baked.
// ODD corners (1,3) are stored with their channel HALVES SWAPPED (ch4-7 first)
// to enable the SEL-free XOR-layout reduction in the main kernel. 12 MB.
__device__ uint4 g_planes_q[3 * RES * RES * 4];

// ---------------------------------------------------------------------------
// Prolog (tiled): one block = 16x16 output tile. Project the 17x17 halo tile
// into smem ONCE per texel (bias/3 added), then emit 256 quad records with a
// corner-transposed loop (warp stores 512B contiguous). Odd-corner records
// are stored half-swapped.
// ---------------------------------------------------------------------------
__global__ void __launch_bounds__(256)
build_quads_kernel(const float* __restrict__ pxy,
                   const float* __restrict__ pxz,
                   const float* __restrict__ pyz,
                   const float* __restrict__ W,
                   const float* __restrict__ B)
{
    const int p = blockIdx.z;
    const float* __restrict__ src = (p == 0) ? pxy : ((p == 1) ? pxz : pyz);

    __shared__ float w[OUTC][RANK];
    __shared__ float b3[OUTC];
    __shared__ uint4 tile[17][19];   // padded stride, conflict-free reads

    int tid = threadIdx.x;
    if (tid < OUTC * RANK) {
        int o = tid / RANK, k = tid % RANK;
        w[o][k] = W[o * (3 * RANK) + p * RANK + k];
    }
    if (tid < OUTC) b3[tid] = B[tid] * (1.f / 3.f);
    __syncthreads();

    int bx = blockIdx.x * 16;
    int by = blockIdx.y * 16;

    for (int l = tid; l < 17 * 17; l += 256) {
        int dy = l / 17, dx = l % 17;
        int sx = min(bx + dx, RES - 1);
        int sy = min(by + dy, RES - 1);
        const float* in = src + (size_t)(sy * RES + sx) * RANK;
        float4 i0 = __ldg((const float4*)(in));
        float4 i1 = __ldg((const float4*)(in + 4));
        float4 i2 = __ldg((const float4*)(in + 8));
        float f[RANK] = { i0.x,i0.y,i0.z,i0.w, i1.x,i1.y,i1.z,i1.w,
                          i2.x,i2.y,i2.z,i2.w };
        float o[OUTC];
        #pragma unroll
        for (int c = 0; c < OUTC; c++) {
            float s = b3[c];
            #pragma unroll
            for (int k = 0; k < RANK; k++) s = fmaf(f[k], w[c][k], s);
            o[c] = s;
        }
        __half2 h0 = __floats2half2_rn(o[0], o[1]);
        __half2 h1 = __floats2half2_rn(o[2], o[3]);
        __half2 h2 = __floats2half2_rn(o[4], o[5]);
        __half2 h3 = __floats2half2_rn(o[6], o[7]);
        uint4 r;
        r.x = HU(h0); r.y = HU(h1); r.z = HU(h2); r.w = HU(h3);
        tile[dy][dx] = r;
    }
    __syncthreads();

    // corner-transposed emit; odd corners stored half-swapped
    int c  = tid & 3;            // corner: bit0 = x side, bit1 = y side
    int t0 = tid >> 2;           // first texel handled by this thread
    #pragma unroll
    for (int i = 0; i < 4; i++) {
        int tex = t0 + i * 64;           // 0..255 within tile
        int dx = tex & 15, dy = tex >> 4;
        uint4 v = tile[dy + (c >> 1)][dx + (c & 1)];
        if (c & 1) v = make_uint4(v.z, v.w, v.x, v.y);   // half-swap
        int texel = (by + dy) * RES + (bx + dx);
        g_planes_q[((((size_t)((p << 16) | texel)) << 2)) + c] = v;
    }
}

// ---------------------------------------------------------------------------
// Main kernel: 4 lanes per 2 points; lane c = corner c of both points.
// Lanes 0,1 treat point A as "first" (F), lanes 2,3 treat point B as first.
// XOR register layout: lane c's P[j] holds half-group h = j^c
//   (h bit1 = point, bit0 = channel-half; half-swap pre-baked in table),
// so the quad reduction is 6 SHFL + 6 HADD2 with fixed register indices.
// ---------------------------------------------------------------------------
__device__ __forceinline__ void point_accum(float cx, float cy, float cz,
                                            int c, float sx, float ox,
                                            float sy, float oy,
                                            __half2 acc[4])
{
    // unnormalize + clamp via FFMA.SAT (subsumes coord clip)
    float tx = 255.f * __saturatef(fmaf(cx, 128.f / 255.f, 0.5f));
    float ty = 255.f * __saturatef(fmaf(cy, 128.f / 255.f, 0.5f));
    float tz = 255.f * __saturatef(fmaf(cz, 128.f / 255.f, 0.5f));
    float fx = floorf(tx), fy = floorf(ty), fz = floorf(tz);
    float wx = tx - fx, wy = ty - fy, wz = tz - fz;
    int x0 = (int)fx, y0 = (int)fy, z0 = (int)fz;

    // lane-side weights: first-axis uses corner bit0 (sx,ox), second-axis bit1
    float u_x = fmaf(sx, wx, ox);   // x as first axis (planes xy, xz)
    float u_y = fmaf(sx, wy, ox);   // y as first axis (plane yz)
    float v_y = fmaf(sy, wy, oy);   // y as second axis (plane xy)
    float v_z = fmaf(sy, wz, oy);   // z as second axis (planes xz, yz)

    __half2 w0 = __float2half2_rn(u_x * v_y);
    __half2 w1 = __float2half2_rn(u_x * v_z);
    __half2 w2 = __float2half2_rn(u_y * v_z);

    int o0 = ((          (y0 << 8) | x0) << 2) + c;
    int o1 = (((1 << 16) | (z0 << 8) | x0) << 2) + c;
    int o2 = (((2 << 16) | (z0 << 8) | y0) << 2) + c;

    uint4 a = __ldg(&g_planes_q[o0]);
    uint4 b = __ldg(&g_planes_q[o1]);
    uint4 d = __ldg(&g_planes_q[o2]);

    acc[0] = __hfma2(U2H(a.x), w0, acc[0]);
    acc[1] = __hfma2(U2H(a.y), w0, acc[1]);
    acc[2] = __hfma2(U2H(a.z), w0, acc[2]);
    acc[3] = __hfma2(U2H(a.w), w0, acc[3]);
    acc[0] = __hfma2(U2H(b.x), w1, acc[0]);
    acc[1] = __hfma2(U2H(b.y), w1, acc[1]);
    acc[2] = __hfma2(U2H(b.z), w1, acc[2]);
    acc[3] = __hfma2(U2H(b.w), w1, acc[3]);
    acc[0] = __hfma2(U2H(d.x), w2, acc[0]);
    acc[1] = __hfma2(U2H(d.y), w2, acc[1]);
    acc[2] = __hfma2(U2H(d.z), w2, acc[2]);
    acc[3] = __hfma2(U2H(d.w), w2, acc[3]);
}

__device__ __forceinline__ __half2 hshfl_add(__half2 v, __half2 src, int lanemask) {
    unsigned int u = HU(src);
    unsigned int s = __shfl_xor_sync(0xffffffffu, u, lanemask);
    return __hadd2(v, U2H(s));
}

__global__ void __launch_bounds__(256)
geo_encoder_kernel(const float* __restrict__ coords,
                   float* __restrict__ out,
                   int N)
{
    int t = blockIdx.x * blockDim.x + threadIdx.x;
    int g = t >> 2;              // point-pair index (points 2g, 2g+1)
    int iA = 2 * g;
    if (iA >= N) return;
    int c = t & 3;               // corner: bit0 = x side, bit1 = y side
    bool hasB = (iA + 1) < N;
    bool second = (c & 2) != 0;  // lanes 2,3: first point = B

    // coords: 2 lane-loads + 6 shuffles (+4 SELs for the F/S rename)
    size_t base = 6 * (size_t)g;
    float v0 = (c < 3 || hasB) ? __ldg(coords + base + c) : 0.f;
    float v1 = (c < 2 && hasB) ? __ldg(coords + base + 4 + c) : 0.f;
    int sF = second ? 3 : 0;                         // x source lane for F
    float cxF = __shfl_sync(0xffffffffu, v0, sF, 4);
    float cxS = __shfl_sync(0xffffffffu, v0, 3 - sF, 4);
    float yA = __shfl_sync(0xffffffffu, v0, 1, 4);
    float zA = __shfl_sync(0xffffffffu, v0, 2, 4);
    float yB = __shfl_sync(0xffffffffu, v1, 0, 4);
    float zB = __shfl_sync(0xffffffffu, v1, 1, 4);
    float cyF = second ? yB : yA;
    float czF = second ? zB : zA;
    float cyS = second ? yA : yB;
    float czS = second ? zA : zB;

    float fxc = (float)(c & 1);
    float fyc = (float)(c >> 1);
    float sx = 2.f * fxc - 1.f, ox = 1.f - fxc;
    float sy = 2.f * fyc - 1.f, oy = 1.f - fyc;

    __half2 z = __float2half2_rn(0.f);
    __half2 accF[4] = { z, z, z, z };   // P[0]=accF[0..1] (h=c), P[1]=accF[2..3]
    __half2 accS[4] = { z, z, z, z };   // P[2]=accS[0..1], P[3]=accS[2..3]

    point_accum(cxF, cyF, czF, c, sx, ox, sy, oy, accF);
    point_accum(cxS, cyS, czS, c, sx, ox, sy, oy, accS);

    // ── XOR-layout reduction: 6 SHFL + 6 HADD2, no SELs ──
    // round 1 (xor 1): P[0] += partner's P[1]; P[2] += partner's P[3]
    accF[0] = hshfl_add(accF[0], accF[2], 1);
    accF[1] = hshfl_add(accF[1], accF[3], 1);
    accS[0] = hshfl_add(accS[0], accS[2], 1);
    accS[1] = hshfl_add(accS[1], accS[3], 1);
    // round 2 (xor 2): P[0] += partner's P[2]
    accF[0] = hshfl_add(accF[0], accS[0], 2);
    accF[1] = hshfl_add(accF[1], accS[1], 2);

    // lane c's P[0] = fully-reduced half-group h=c = float4 #c of the pair's
    // 64B output record (A ch0-3 | A ch4-7 | B ch0-3 | B ch4-7)
    const __half2 TEN  = __float2half2_rn(10.f);
    const __half2 NTEN = __float2half2_rn(-10.f);
    __half2 s0 = __hmax2(__hmin2(accF[0], TEN), NTEN);
    __half2 s1 = __hmax2(__hmin2(accF[1], TEN), NTEN);

    float2 f0 = __half22float2(s0);
    float2 f1 = __half22float2(s1);

    if (c < 2 || hasB)
        ((float4*)(out + 16 * (size_t)g))[c] = make_float4(f0.x, f0.y, f1.x, f1.y);
}

extern "C" void kernel_launch(void* const* d_in, const int* in_sizes, int n_in,
                              void* d_out, int out_size)
{
    const float* coords = (const float*)d_in[0];
    const float* pxy    = (const float*)d_in[1];
    const float* pxz    = (const float*)d_in[2];
    const float* pyz    = (const float*)d_in[3];
    const float* projw  = (const float*)d_in[4];
    const float* projb  = (const float*)d_in[5];
    float* out = (float*)d_out;

    int N = in_sizes[0] / 3;

    dim3 qgrid(RES / 16, RES / 16, 3);
    build_quads_kernel<<<qgrid, 256>>>(pxy, pxz, pyz, projw, projb);

    long long pairs = (N + 1) / 2;
    long long threads = 4LL * pairs;
    int blocks = (int)((threads + 255) / 256);
    geo_encoder_kernel<<<blocks, 256>>>(coords, out, N);
}

// round 16
// speedup vs baseline: 1.3522x; 1.3522x over previous
#include <cuda_runtime.h>
#include <cuda_fp16.h>
#include <cuda_bf16.h>

#define RES   256
#define RANK  12
#define OUTC  8

#define HU(h)  (*(unsigned int*)&(h))
#define U2H(u) (*(__half2*)&(u))

// Corner-quad records: per (plane,y,x) a 64B record {v00,v01,v10,v11} of
// fp16x8 projected features (+ bias/3 folded in), border clamp baked.
// ODD corners (1,3) store their channel HALVES SWAPPED (ch4-7 first): this is
// table-side only (addresses unchanged) and makes the quad reduction need only
// 8 SHFLs. 12 MB, L2-resident.
__device__ uint4 g_planes_q[3 * RES * RES * 4];

// ---------------------------------------------------------------------------
// Prolog (tiled): one block = 16x16 output tile. Project the 17x17 halo tile
// into smem ONCE per texel (bias/3 added), then emit 256 quad records with a
// corner-transposed loop (warp stores 512B contiguous). Odd corners
// half-swapped.
// ---------------------------------------------------------------------------
__global__ void __launch_bounds__(256)
build_quads_kernel(const float* __restrict__ pxy,
                   const float* __restrict__ pxz,
                   const float* __restrict__ pyz,
                   const float* __restrict__ W,
                   const float* __restrict__ B)
{
    const int p = blockIdx.z;
    const float* __restrict__ src = (p == 0) ? pxy : ((p == 1) ? pxz : pyz);

    __shared__ float w[OUTC][RANK];
    __shared__ float b3[OUTC];
    __shared__ uint4 tile[17][19];   // padded stride, conflict-free reads

    int tid = threadIdx.x;
    if (tid < OUTC * RANK) {
        int o = tid / RANK, k = tid % RANK;
        w[o][k] = W[o * (3 * RANK) + p * RANK + k];
    }
    if (tid < OUTC) b3[tid] = B[tid] * (1.f / 3.f);
    __syncthreads();

    int bx = blockIdx.x * 16;
    int by = blockIdx.y * 16;

    for (int l = tid; l < 17 * 17; l += 256) {
        int dy = l / 17, dx = l % 17;
        int sx = min(bx + dx, RES - 1);
        int sy = min(by + dy, RES - 1);
        const float* in = src + (size_t)(sy * RES + sx) * RANK;
        float4 i0 = __ldg((const float4*)(in));
        float4 i1 = __ldg((const float4*)(in + 4));
        float4 i2 = __ldg((const float4*)(in + 8));
        float f[RANK] = { i0.x,i0.y,i0.z,i0.w, i1.x,i1.y,i1.z,i1.w,
                          i2.x,i2.y,i2.z,i2.w };
        float o[OUTC];
        #pragma unroll
        for (int c = 0; c < OUTC; c++) {
            float s = b3[c];
            #pragma unroll
            for (int k = 0; k < RANK; k++) s = fmaf(f[k], w[c][k], s);
            o[c] = s;
        }
        __half2 h0 = __floats2half2_rn(o[0], o[1]);
        __half2 h1 = __floats2half2_rn(o[2], o[3]);
        __half2 h2 = __floats2half2_rn(o[4], o[5]);
        __half2 h3 = __floats2half2_rn(o[6], o[7]);
        uint4 r;
        r.x = HU(h0); r.y = HU(h1); r.z = HU(h2); r.w = HU(h3);
        tile[dy][dx] = r;
    }
    __syncthreads();

    // corner-transposed emit; odd corners stored half-swapped
    int c  = tid & 3;            // corner: bit0 = x side, bit1 = y side
    int t0 = tid >> 2;           // first texel handled by this thread
    #pragma unroll
    for (int i = 0; i < 4; i++) {
        int tex = t0 + i * 64;           // 0..255 within tile
        int dx = tex & 15, dy = tex >> 4;
        uint4 v = tile[dy + (c >> 1)][dx + (c & 1)];
        if (c & 1) v = make_uint4(v.z, v.w, v.x, v.y);   // half-swap
        int texel = (by + dy) * RES + (bx + dx);
        g_planes_q[((((size_t)((p << 16) | texel)) << 2)) + c] = v;
    }
}

// ---------------------------------------------------------------------------
// Main kernel: 4 lanes per 2 points; lane c = corner c of BOTH points (A
// first, B second — address-uniform: every gather LDG hits ONE 64B record per
// group = 1 L1 wavefront). Half-swapped table makes lane c's acc[0..1] hold
// channel-half (c&1): quad reduction = 8 SHFL + 8 HADD2, no data SELs.
// ---------------------------------------------------------------------------
__device__ __forceinline__ void point_accum(float cx, float cy, float cz,
                                            int c, float sx, float ox,
                                            float sy, float oy,
                                            __half2 acc[4])
{
    // unnormalize + clamp via FFMA.SAT (subsumes coord clip)
    float tx = 255.f * __saturatef(fmaf(cx, 128.f / 255.f, 0.5f));
    float ty = 255.f * __saturatef(fmaf(cy, 128.f / 255.f, 0.5f));
    float tz = 255.f * __saturatef(fmaf(cz, 128.f / 255.f, 0.5f));
    float fx = floorf(tx), fy = floorf(ty), fz = floorf(tz);
    float wx = tx - fx, wy = ty - fy, wz = tz - fz;
    int x0 = (int)fx, y0 = (int)fy, z0 = (int)fz;

    // lane-side weights: first-axis uses corner bit0 (sx,ox), second-axis bit1
    float u_x = fmaf(sx, wx, ox);   // x as first axis (planes xy, xz)
    float u_y = fmaf(sx, wy, ox);   // y as first axis (plane yz)
    float v_y = fmaf(sy, wy, oy);   // y as second axis (plane xy)
    float v_z = fmaf(sy, wz, oy);   // z as second axis (planes xz, yz)

    __half2 w0 = __float2half2_rn(u_x * v_y);
    __half2 w1 = __float2half2_rn(u_x * v_z);
    __half2 w2 = __float2half2_rn(u_y * v_z);

    int o0 = ((          (y0 << 8) | x0) << 2) + c;
    int o1 = (((1 << 16) | (z0 << 8) | x0) << 2) + c;
    int o2 = (((2 << 16) | (z0 << 8) | y0) << 2) + c;

    uint4 a = __ldg(&g_planes_q[o0]);
    uint4 b = __ldg(&g_planes_q[o1]);
    uint4 d = __ldg(&g_planes_q[o2]);

    acc[0] = __hfma2(U2H(a.x), w0, acc[0]);
    acc[1] = __hfma2(U2H(a.y), w0, acc[1]);
    acc[2] = __hfma2(U2H(a.z), w0, acc[2]);
    acc[3] = __hfma2(U2H(a.w), w0, acc[3]);
    acc[0] = __hfma2(U2H(b.x), w1, acc[0]);
    acc[1] = __hfma2(U2H(b.y), w1, acc[1]);
    acc[2] = __hfma2(U2H(b.z), w1, acc[2]);
    acc[3] = __hfma2(U2H(b.w), w1, acc[3]);
    acc[0] = __hfma2(U2H(d.x), w2, acc[0]);
    acc[1] = __hfma2(U2H(d.y), w2, acc[1]);
    acc[2] = __hfma2(U2H(d.z), w2, acc[2]);
    acc[3] = __hfma2(U2H(d.w), w2, acc[3]);
}

__device__ __forceinline__ __half2 hshfl_add(__half2 v, __half2 src, int lanemask) {
    unsigned int u = HU(src);
    unsigned int s = __shfl_xor_sync(0xffffffffu, u, lanemask);
    return __hadd2(v, U2H(s));
}

__global__ void __launch_bounds__(256)
geo_encoder_kernel(const float* __restrict__ coords,
                   float* __restrict__ out,
                   int N)
{
    int t = blockIdx.x * blockDim.x + threadIdx.x;
    int g = t >> 2;              // point-pair index (points 2g, 2g+1)
    int iA = 2 * g;
    if (iA >= N) return;
    int c = t & 3;               // corner: bit0 = x side, bit1 = y side
    bool hasB = (iA + 1) < N;

    // coords for both points: 2 lane-loads + 6 narrow shuffles (R11 exact)
    size_t base = 6 * (size_t)g;
    float v0 = (c < 3 || hasB) ? __ldg(coords + base + c) : 0.f;
    float v1 = (c < 2 && hasB) ? __ldg(coords + base + 4 + c) : 0.f;
    float cxA = __shfl_sync(0xffffffffu, v0, 0, 4);
    float cyA = __shfl_sync(0xffffffffu, v0, 1, 4);
    float czA = __shfl_sync(0xffffffffu, v0, 2, 4);
    float cxB = __shfl_sync(0xffffffffu, v0, 3, 4);
    float cyB = __shfl_sync(0xffffffffu, v1, 0, 4);
    float czB = __shfl_sync(0xffffffffu, v1, 1, 4);

    float fxc = (float)(c & 1);
    float fyc = (float)(c >> 1);
    float sx = 2.f * fxc - 1.f, ox = 1.f - fxc;
    float sy = 2.f * fyc - 1.f, oy = 1.f - fyc;

    __half2 z = __float2half2_rn(0.f);
    __half2 accA[4] = { z, z, z, z };   // [0..1] = half (c&1), [2..3] = other
    __half2 accB[4] = { z, z, z, z };

    point_accum(cxA, cyA, czA, c, sx, ox, sy, oy, accA);
    if (hasB) point_accum(cxB, cyB, czB, c, sx, ox, sy, oy, accB);

    // ── half-swapped quad reduction: 8 SHFL + 8 HADD2, no data SELs ──
    // round 1 (xor 1): partner's acc[2..3] holds MY half by construction
    accA[0] = hshfl_add(accA[0], accA[2], 1);
    accA[1] = hshfl_add(accA[1], accA[3], 1);
    accB[0] = hshfl_add(accB[0], accB[2], 1);
    accB[1] = hshfl_add(accB[1], accB[3], 1);
    // round 2 (xor 2): partner holds the SAME half -> plain allreduce
    accA[0] = hshfl_add(accA[0], accA[0], 2);
    accA[1] = hshfl_add(accA[1], accA[1], 2);
    accB[0] = hshfl_add(accB[0], accB[0], 2);
    accB[1] = hshfl_add(accB[1], accB[1], 2);

    // lane c now holds half (c&1) of BOTH points; pick point by bit1:
    // output float4 #c = point (c>>1), channels [(c&1)*4 .. (c&1)*4+3]
    __half2 s0 = (c & 2) ? accB[0] : accA[0];
    __half2 s1 = (c & 2) ? accB[1] : accA[1];

    // clamp [-10,10] in half2, then upconvert (bias already folded into quads)
    const __half2 TEN  = __float2half2_rn(10.f);
    const __half2 NTEN = __float2half2_rn(-10.f);
    s0 = __hmax2(__hmin2(s0, TEN), NTEN);
    s1 = __hmax2(__hmin2(s1, TEN), NTEN);

    float2 f0 = __half22float2(s0);
    float2 f1 = __half22float2(s1);

    if (c < 2 || hasB)
        ((float4*)(out + 16 * (size_t)g))[c] = make_float4(f0.x, f0.y, f1.x, f1.y);
}

extern "C" void kernel_launch(void* const* d_in, const int* in_sizes, int n_in,
                              void* d_out, int out_size)
{
    const float* coords = (const float*)d_in[0];
    const float* pxy    = (const float*)d_in[1];
    const float* pxz    = (const float*)d_in[2];
    const float* pyz    = (const float*)d_in[3];
    const float* projw  = (const float*)d_in[4];
    const float* projb  = (const float*)d_in[5];
    float* out = (float*)d_out;

    int N = in_sizes[0] / 3;

    dim3 qgrid(RES / 16, RES / 16, 3);
    build_quads_kernel<<<qgrid, 256>>>(pxy, pxz, pyz, projw, projb);

    long long pairs = (N + 1) / 2;
    long long threads = 4LL * pairs;
    int blocks = (int)((threads + 255) / 256);
    geo_encoder_kernel<<<blocks, 256>>>(coords, out, N);
}